// round 2
// baseline (speedup 1.0000x reference)
#include <cuda_runtime.h>
#include <cstdint>

#define Bv 4
#define Nv 512
#define Dv 256
#define Lv 64

// Scratch for projected features, transposed layout [b][l][n]  (512 KB)
__device__ float g_xh[Bv * Lv * Nv];

// ---------------------------------------------------------------------------
// Packed f32x2 helpers (sm_103a FFMA2/FADD2 path)
// ---------------------------------------------------------------------------
__device__ __forceinline__ unsigned long long pk2(float a) {
    unsigned long long r;
    asm("mov.b64 %0, {%1, %2};" : "=l"(r) : "f"(a), "f"(a));
    return r;
}
__device__ __forceinline__ unsigned long long add2(unsigned long long a,
                                                   unsigned long long b) {
    unsigned long long r;
    asm("add.rn.f32x2 %0, %1, %2;" : "=l"(r) : "l"(a), "l"(b));
    return r;
}
__device__ __forceinline__ unsigned long long fma2(unsigned long long a,
                                                   unsigned long long b,
                                                   unsigned long long c) {
    unsigned long long r;
    asm("fma.rn.f32x2 %0, %1, %2, %3;" : "=l"(r) : "l"(a), "l"(b), "l"(c));
    return r;
}

// ---------------------------------------------------------------------------
// Kernel 1: x_hat[b,n,l] = sum_d x[b,n,d] * W[l,d], written as g_xh[b][l][n]
// ---------------------------------------------------------------------------
__global__ __launch_bounds__(256) void proj_kernel(const float* __restrict__ x,
                                                   const float* __restrict__ W) {
    extern __shared__ float sm[];
    float* xs = sm;                 // [256][17]  x tile transposed, padded
    float* Wt = sm + 256 * 17;      // [256][68]  W transposed, padded

    int b  = blockIdx.x >> 5;
    int n0 = (blockIdx.x & 31) << 4;
    int tid = threadIdx.x;

    for (int idx = tid; idx < 16 * 256; idx += 256) {
        int rr = idx >> 8, d = idx & 255;
        xs[d * 17 + rr] = x[(b * Nv + n0 + rr) * Dv + d];
    }
    for (int idx = tid; idx < 64 * 256; idx += 256) {
        int l = idx >> 8, d = idx & 255;
        Wt[d * 68 + l] = W[l * Dv + d];
    }
    __syncthreads();

    int r  = tid & 15;
    int l0 = (tid >> 4) << 2;

    float a0 = 0.f, a1 = 0.f, a2 = 0.f, a3 = 0.f;
#pragma unroll 8
    for (int d = 0; d < 256; ++d) {
        float  xv = xs[d * 17 + r];
        float4 wq = *(const float4*)&Wt[d * 68 + l0];
        a0 = fmaf(xv, wq.x, a0);
        a1 = fmaf(xv, wq.y, a1);
        a2 = fmaf(xv, wq.z, a2);
        a3 = fmaf(xv, wq.w, a3);
    }
    float* dst = g_xh + b * (Lv * Nv) + n0 + r;
    dst[(l0 + 0) * Nv] = a0;
    dst[(l0 + 1) * Nv] = a1;
    dst[(l0 + 2) * Nv] = a2;
    dst[(l0 + 3) * Nv] = a3;
}

// ---------------------------------------------------------------------------
// Kernel 2: fused dist + leaky_relu + row normalization.
// 512 threads = 16 warps. Warp layout: pair = w&7 owns rows {2p, 2p+1},
// jh = w>>3 selects j half [jh*256, jh*256+256). Each lane: 8 j per row
// (2 float4 groups at jbase and jbase+128), accumulators packed f32x2.
// ---------------------------------------------------------------------------
__global__ __launch_bounds__(512, 1) void dist_softmax_kernel(
    const float* __restrict__ adj, const float* __restrict__ lw,
    float* __restrict__ out) {
    extern __shared__ float sm[];
    float* sj  = sm;                      // [64][512] x_hat[b], l-major
    float* si  = sm + Lv * Nv;            // [16][64]  tile's i rows, l fast
    float* ws  = si + 16 * 64;            // [64]      learn_w
    float* red = ws + 64;                 // [64] reduction scratch

    int b  = blockIdx.x >> 5;
    int i0 = (blockIdx.x & 31) << 4;
    int tid = threadIdx.x;

    const float* xh = g_xh + b * (Lv * Nv);
    for (int idx = tid; idx < (Lv * Nv) / 4; idx += 512)
        ((float4*)sj)[idx] = ((const float4*)xh)[idx];
    for (int idx = tid; idx < 16 * 64; idx += 512) {
        int il = idx >> 6, l = idx & 63;
        si[idx] = xh[l * Nv + i0 + il];
    }
    if (tid < 64) ws[tid] = lw[tid];
    __syncthreads();

    int w    = tid >> 5;
    int lane = tid & 31;
    int pair = w & 7;
    int jh   = w >> 3;
    int ia = i0 + 2 * pair;
    int ib = ia + 1;
    const float* pa = si + (2 * pair) * 64;
    const float* pb = pa + 64;
    int jbase = jh * 256 + lane * 4;

    const unsigned long long ABS2 = 0x7FFFFFFF7FFFFFFFull;
    unsigned long long accA0 = 0, accA1 = 0, accA2 = 0, accA3 = 0;
    unsigned long long accB0 = 0, accB1 = 0, accB2 = 0, accB3 = 0;

#pragma unroll 2
    for (int l4 = 0; l4 < 16; ++l4) {
        float4 w4  = *(const float4*)&ws[l4 * 4];
        float4 va4 = *(const float4*)&pa[l4 * 4];
        float4 vb4 = *(const float4*)&pb[l4 * 4];
#pragma unroll
        for (int c = 0; c < 4; ++c) {
            int l = l4 * 4 + c;
            float wv = ((const float*)&w4)[c];
            float na = -((const float*)&va4)[c];
            float nb = -((const float*)&vb4)[c];
            unsigned long long w2  = pk2(wv);
            unsigned long long na2 = pk2(na);
            unsigned long long nb2 = pk2(nb);
            ulonglong2 j0 = *(const ulonglong2*)(sj + l * Nv + jbase);
            ulonglong2 j1 = *(const ulonglong2*)(sj + l * Nv + jbase + 128);
            accA0 = fma2(w2, add2(j0.x, na2) & ABS2, accA0);
            accA1 = fma2(w2, add2(j0.y, na2) & ABS2, accA1);
            accA2 = fma2(w2, add2(j1.x, na2) & ABS2, accA2);
            accA3 = fma2(w2, add2(j1.y, na2) & ABS2, accA3);
            accB0 = fma2(w2, add2(j0.x, nb2) & ABS2, accB0);
            accB1 = fma2(w2, add2(j0.y, nb2) & ABS2, accB1);
            accB2 = fma2(w2, add2(j1.x, nb2) & ABS2, accB2);
            accB3 = fma2(w2, add2(j1.y, nb2) & ABS2, accB3);
        }
    }

    // unpack accumulators: da[0..3] = jbase+0..3, da[4..7] = jbase+128+0..3
    float da[8], db[8];
    {
        const float* p;
        p = (const float*)&accA0; da[0] = p[0]; da[1] = p[1];
        p = (const float*)&accA1; da[2] = p[0]; da[3] = p[1];
        p = (const float*)&accA2; da[4] = p[0]; da[5] = p[1];
        p = (const float*)&accA3; da[6] = p[0]; da[7] = p[1];
        p = (const float*)&accB0; db[0] = p[0]; db[1] = p[1];
        p = (const float*)&accB1; db[2] = p[0]; db[3] = p[1];
        p = (const float*)&accB2; db[4] = p[0]; db[5] = p[1];
        p = (const float*)&accB3; db[6] = p[0]; db[7] = p[1];
    }

    // leaky_relu + warp-partial max (over this warp's 256 j)
    float ma = -1e30f, mb = -1e30f;
#pragma unroll
    for (int k = 0; k < 8; ++k) {
        float d = da[k]; d = d > 0.f ? d : 0.01f * d; da[k] = d; ma = fmaxf(ma, d);
        float e = db[k]; e = e > 0.f ? e : 0.01f * e; db[k] = e; mb = fmaxf(mb, e);
    }
#pragma unroll
    for (int o = 16; o; o >>= 1) {
        ma = fmaxf(ma, __shfl_xor_sync(0xffffffffu, ma, o));
        mb = fmaxf(mb, __shfl_xor_sync(0xffffffffu, mb, o));
    }
    if (lane == 0) {
        red[jh * 16 + pair * 2 + 0] = ma;
        red[jh * 16 + pair * 2 + 1] = mb;
    }
    __syncthreads();
    float Ma = fmaxf(red[pair * 2 + 0], red[16 + pair * 2 + 0]);
    float Mb = fmaxf(red[pair * 2 + 1], red[16 + pair * 2 + 1]);

    // adj * exp(d - max), warp-partial sums
    const float* adja = adj + (size_t)(b * Nv + ia) * Nv;
    const float* adjb = adj + (size_t)(b * Nv + ib) * Nv;
    float4 av0 = *(const float4*)&adja[jbase];
    float4 av1 = *(const float4*)&adja[jbase + 128];
    float4 bv0 = *(const float4*)&adjb[jbase];
    float4 bv1 = *(const float4*)&adjb[jbase + 128];
    float sa = 0.f, sb = 0.f;
    {
        float v;
        v = av0.x * __expf(da[0] - Ma); da[0] = v; sa += v;
        v = av0.y * __expf(da[1] - Ma); da[1] = v; sa += v;
        v = av0.z * __expf(da[2] - Ma); da[2] = v; sa += v;
        v = av0.w * __expf(da[3] - Ma); da[3] = v; sa += v;
        v = av1.x * __expf(da[4] - Ma); da[4] = v; sa += v;
        v = av1.y * __expf(da[5] - Ma); da[5] = v; sa += v;
        v = av1.z * __expf(da[6] - Ma); da[6] = v; sa += v;
        v = av1.w * __expf(da[7] - Ma); da[7] = v; sa += v;
        v = bv0.x * __expf(db[0] - Mb); db[0] = v; sb += v;
        v = bv0.y * __expf(db[1] - Mb); db[1] = v; sb += v;
        v = bv0.z * __expf(db[2] - Mb); db[2] = v; sb += v;
        v = bv0.w * __expf(db[3] - Mb); db[3] = v; sb += v;
        v = bv1.x * __expf(db[4] - Mb); db[4] = v; sb += v;
        v = bv1.y * __expf(db[5] - Mb); db[5] = v; sb += v;
        v = bv1.z * __expf(db[6] - Mb); db[6] = v; sb += v;
        v = bv1.w * __expf(db[7] - Mb); db[7] = v; sb += v;
    }
#pragma unroll
    for (int o = 16; o; o >>= 1) {
        sa += __shfl_xor_sync(0xffffffffu, sa, o);
        sb += __shfl_xor_sync(0xffffffffu, sb, o);
    }
    if (lane == 0) {
        red[32 + jh * 16 + pair * 2 + 0] = sa;
        red[32 + jh * 16 + pair * 2 + 1] = sb;
    }
    __syncthreads();
    float ra = 1.0f / (red[32 + pair * 2 + 0] + red[32 + 16 + pair * 2 + 0]);
    float rb = 1.0f / (red[32 + pair * 2 + 1] + red[32 + 16 + pair * 2 + 1]);

    float* oa = out + (size_t)(b * Nv + ia) * Nv;
    float* ob = out + (size_t)(b * Nv + ib) * Nv;
    float4 o4;
    o4.x = da[0] * ra + 1e-10f; o4.y = da[1] * ra + 1e-10f;
    o4.z = da[2] * ra + 1e-10f; o4.w = da[3] * ra + 1e-10f;
    *(float4*)&oa[jbase] = o4;
    o4.x = da[4] * ra + 1e-10f; o4.y = da[5] * ra + 1e-10f;
    o4.z = da[6] * ra + 1e-10f; o4.w = da[7] * ra + 1e-10f;
    *(float4*)&oa[jbase + 128] = o4;
    o4.x = db[0] * rb + 1e-10f; o4.y = db[1] * rb + 1e-10f;
    o4.z = db[2] * rb + 1e-10f; o4.w = db[3] * rb + 1e-10f;
    *(float4*)&ob[jbase] = o4;
    o4.x = db[4] * rb + 1e-10f; o4.y = db[5] * rb + 1e-10f;
    o4.z = db[6] * rb + 1e-10f; o4.w = db[7] * rb + 1e-10f;
    *(float4*)&ob[jbase + 128] = o4;
}

extern "C" void kernel_launch(void* const* d_in, const int* in_sizes, int n_in,
                              void* d_out, int out_size) {
    (void)in_sizes; (void)n_in; (void)out_size;
    const float* x   = (const float*)d_in[0];
    const float* adj = (const float*)d_in[1];
    const float* W   = (const float*)d_in[2];
    const float* lw  = (const float*)d_in[3];
    float* out = (float*)d_out;

    const int smem1 = (256 * 17 + 256 * 68) * 4;
    const int smem2 = (Lv * Nv + 16 * 64 + 64 + 64) * 4;
    cudaFuncSetAttribute(proj_kernel,
                         cudaFuncAttributeMaxDynamicSharedMemorySize, smem1);
    cudaFuncSetAttribute(dist_softmax_kernel,
                         cudaFuncAttributeMaxDynamicSharedMemorySize, smem2);

    proj_kernel<<<Bv * (Nv / 16), 256, smem1>>>(x, W);
    dist_softmax_kernel<<<Bv * (Nv / 16), 512, smem2>>>(adj, lw, out);
}